// round 15
// baseline (speedup 1.0000x reference)
#include <cuda_runtime.h>
#include <cstdint>

#define N_NODES 100000
#define N_EDGES 1600000
#define NHID 64
#define NCLASS 40
#define SCAN_B 512
#define NBLK ((N_NODES + SCAN_B - 1) / SCAN_B)   // 196

// Scratch (static device globals — no allocation)
__device__ float g_agg[N_NODES * NHID];
__device__ float g_h[N_NODES * NHID];
__device__ int   g_deg[N_NODES];
__device__ int   g_off[N_NODES];
__device__ int   g_cur[N_NODES];
__device__ int   g_adj[N_EDGES];
__device__ int   g_bsum[NBLK];

// ---------------------------------------------------------------------------
// Edge-index dtype detection (int64 vs x64-disabled int32)
// ---------------------------------------------------------------------------
__device__ __forceinline__ bool ei_is64(const void* ei_raw) {
    const long long* e = (const long long*)ei_raw;
    return ((unsigned long long)e[0] < (1ULL << 32)) &&
           ((unsigned long long)e[1] < (1ULL << 32)) &&
           ((unsigned long long)e[2] < (1ULL << 32));
}

// Load 4 consecutive edge indices starting at i (i % 4 == 0) from row `row`
// (0 = src row, 1 = dst row) with one/two vector loads.
__device__ __forceinline__ void ei_load4(const void* ei_raw, bool is64,
                                         int row, int i, int v[4]) {
    if (is64) {
        const longlong2* p =
            (const longlong2*)((const long long*)ei_raw + (size_t)row * N_EDGES + i);
        longlong2 a = p[0], b = p[1];
        v[0] = (int)a.x; v[1] = (int)a.y; v[2] = (int)b.x; v[3] = (int)b.y;
    } else {
        const int4* p = (const int4*)((const int*)ei_raw + (size_t)row * N_EDGES + i);
        int4 a = p[0];
        v[0] = a.x; v[1] = a.y; v[2] = a.z; v[3] = a.w;
    }
}

// ---------------------------------------------------------------------------
// CSR construction — 4 edges per thread (4 independent atomic chains, vector
// index loads) to hide ATOMG/REDG latency (R13 profile: issue=5%, occ=81%).
// ---------------------------------------------------------------------------
__global__ void hist_kernel(const void* __restrict__ ei, int* __restrict__ deg) {
    int base = (blockIdx.x * blockDim.x + threadIdx.x) * 4;
    if (base >= N_EDGES) return;
    bool is64 = ei_is64(ei);
    int d[4];
    ei_load4(ei, is64, 1, base, d);
    #pragma unroll
    for (int k = 0; k < 4; k++) atomicAdd(&deg[d[k]], 1);   // no return -> RED
}

// scan phase A: per-block sums of 512 deg entries
__global__ __launch_bounds__(SCAN_B) void scanA_kernel(
    const int* __restrict__ deg, int* __restrict__ bsum)
{
    __shared__ int s[SCAN_B];
    int t = threadIdx.x;
    int i = blockIdx.x * SCAN_B + t;
    s[t] = (i < N_NODES) ? deg[i] : 0;
    __syncthreads();
    #pragma unroll
    for (int k = SCAN_B / 2; k > 0; k >>= 1) {
        if (t < k) s[t] += s[t + k];
        __syncthreads();
    }
    if (t == 0) bsum[blockIdx.x] = s[0];
}

// scan phase C (fused base): each block reduces bsum[j], j < blockIdx.x, then
// Hillis-Steele scans its own 512 degs. (No grid=1 scanB kernel.)
__global__ __launch_bounds__(SCAN_B) void scanC_kernel(
    const int* __restrict__ deg, const int* __restrict__ bsum,
    int* __restrict__ off, int* __restrict__ cur)
{
    __shared__ int sa[SCAN_B], sb[SCAN_B];
    int t = threadIdx.x;

    sa[t] = (t < NBLK && t < blockIdx.x) ? bsum[t] : 0;
    __syncthreads();
    #pragma unroll
    for (int k = SCAN_B / 2; k > 0; k >>= 1) {
        if (t < k) sa[t] += sa[t + k];
        __syncthreads();
    }
    int base = sa[0];
    __syncthreads();

    int i = blockIdx.x * SCAN_B + t;
    int v = (i < N_NODES) ? deg[i] : 0;
    sa[t] = v;
    __syncthreads();
    int* src = sa; int* dst = sb;
    #pragma unroll
    for (int k = 1; k < SCAN_B; k <<= 1) {
        dst[t] = (t >= k) ? src[t] + src[t - k] : src[t];
        __syncthreads();
        int* tmp = src; src = dst; dst = tmp;
    }
    if (i < N_NODES) {
        int excl = base + src[t] - v;
        off[i] = excl;
        cur[i] = excl;
    }
}

__global__ void fill_kernel(const void* __restrict__ ei,
                            int* __restrict__ cur, int* __restrict__ adj) {
    int base = (blockIdx.x * blockDim.x + threadIdx.x) * 4;
    if (base >= N_EDGES) return;
    bool is64 = ei_is64(ei);
    int s[4], d[4], pos[4];
    ei_load4(ei, is64, 0, base, s);
    ei_load4(ei, is64, 1, base, d);
    #pragma unroll
    for (int k = 0; k < 4; k++) pos[k] = atomicAdd(&cur[d[k]], 1);
    #pragma unroll
    for (int k = 0; k < 4; k++) adj[pos[k]] = s[k];
}

// ---------------------------------------------------------------------------
// Pull aggregation: agg[i] = feat[i] + sum_j feat[adj[j]]  (R11 version)
// ---------------------------------------------------------------------------
__global__ __launch_bounds__(256) void aggregate_kernel(
    const float* __restrict__ feat, float* __restrict__ aggout,
    const int* __restrict__ off, const int* __restrict__ deg,
    const int* __restrict__ adj)
{
    int tid = blockIdx.x * blockDim.x + threadIdx.x;
    int node = tid >> 4;
    if (node >= N_NODES) return;
    int q = tid & 15;

    int o = off[node];
    int d = deg[node];

    float4 acc = ((const float4*)(feat + (size_t)node * NHID))[q];   // self term

    int i0 = (d > 0) ? __ldg(adj + o) : 0;
    int i1 = (d > 1) ? __ldg(adj + o + 1) : 0;
    for (int j = 0; j < d; j++) {
        int inext = (j + 2 < d) ? __ldg(adj + o + j + 2) : 0;
        float4 v = ((const float4*)(feat + (size_t)i0 * NHID))[q];
        acc.x += v.x; acc.y += v.y; acc.z += v.z; acc.w += v.w;
        i0 = i1; i1 = inext;
    }
    ((float4*)(aggout + (size_t)node * NHID))[q] = acc;
}

// ---------------------------------------------------------------------------
// out = relu(A @ W + b)   (R11 scalar-FFMA version — known good)
// ---------------------------------------------------------------------------
__global__ __launch_bounds__(256) void gemm_relu_kernel(
    const float* __restrict__ A, const float* __restrict__ W,
    const float* __restrict__ b, float* __restrict__ out, int nrows)
{
    __shared__ __align__(16) float Ws[64 * 64];
    __shared__ float bs[64];
    int t = threadIdx.x;

    const float4* Wg = (const float4*)W;
    float4* Wsv = (float4*)Ws;
    #pragma unroll
    for (int i = 0; i < 4; i++) Wsv[t + i * 256] = Wg[t + i * 256];
    if (t < 64) bs[t] = b[t];
    __syncthreads();

    int cg = t >> 6;
    int rq = t & 63;
    int r0 = blockIdx.x * 256 + rq * 4;

    float acc[4][16];
    #pragma unroll
    for (int rr = 0; rr < 4; rr++)
        #pragma unroll
        for (int c = 0; c < 16; c++) acc[rr][c] = 0.f;

    for (int k = 0; k < 64; k += 4) {
        float xv[4][4];
        #pragma unroll
        for (int rr = 0; rr < 4; rr++) {
            int r = r0 + rr;
            float4 v = (r < nrows)
                ? *reinterpret_cast<const float4*>(A + (size_t)r * 64 + k)
                : make_float4(0.f, 0.f, 0.f, 0.f);
            xv[rr][0] = v.x; xv[rr][1] = v.y; xv[rr][2] = v.z; xv[rr][3] = v.w;
        }
        #pragma unroll
        for (int kk = 0; kk < 4; kk++) {
            const float4* wr = reinterpret_cast<const float4*>(Ws + (k + kk) * 64 + cg * 16);
            float w[16];
            #pragma unroll
            for (int j = 0; j < 4; j++) {
                float4 ww = wr[j];
                w[j*4+0] = ww.x; w[j*4+1] = ww.y; w[j*4+2] = ww.z; w[j*4+3] = ww.w;
            }
            #pragma unroll
            for (int rr = 0; rr < 4; rr++) {
                float a = xv[rr][kk];
                #pragma unroll
                for (int c = 0; c < 16; c++) acc[rr][c] += a * w[c];
            }
        }
    }

    #pragma unroll
    for (int rr = 0; rr < 4; rr++) {
        int r = r0 + rr;
        if (r < nrows) {
            float* op = out + (size_t)r * 64 + cg * 16;
            #pragma unroll
            for (int j = 0; j < 4; j++) {
                float4 o;
                o.x = fmaxf(acc[rr][j*4+0] + bs[cg*16 + j*4+0], 0.f);
                o.y = fmaxf(acc[rr][j*4+1] + bs[cg*16 + j*4+1], 0.f);
                o.z = fmaxf(acc[rr][j*4+2] + bs[cg*16 + j*4+2], 0.f);
                o.w = fmaxf(acc[rr][j*4+3] + bs[cg*16 + j*4+3], 0.f);
                *reinterpret_cast<float4*>(op + j * 4) = o;
            }
        }
    }
}

// ---------------------------------------------------------------------------
// out = log_softmax(A @ Wf + bf)   (R11 version)
// ---------------------------------------------------------------------------
__global__ __launch_bounds__(256) void final_kernel(
    const float* __restrict__ A, const float* __restrict__ W,
    const float* __restrict__ b, float* __restrict__ out, int nrows)
{
    __shared__ __align__(16) float Ws[64 * NCLASS];
    __shared__ float bs[NCLASS];
    int t = threadIdx.x;
    for (int i = t; i < 64 * NCLASS / 4; i += 256)
        ((float4*)Ws)[i] = ((const float4*)W)[i];
    if (t < NCLASS) bs[t] = b[t];
    __syncthreads();

    int r0 = (blockIdx.x * 256 + t) * 2;

    float acc[2][NCLASS];
    #pragma unroll
    for (int rr = 0; rr < 2; rr++)
        #pragma unroll
        for (int c = 0; c < NCLASS; c++) acc[rr][c] = bs[c];

    for (int k = 0; k < 64; k += 4) {
        float xv[2][4];
        #pragma unroll
        for (int rr = 0; rr < 2; rr++) {
            int r = r0 + rr;
            float4 v = (r < nrows)
                ? *reinterpret_cast<const float4*>(A + (size_t)r * 64 + k)
                : make_float4(0.f, 0.f, 0.f, 0.f);
            xv[rr][0] = v.x; xv[rr][1] = v.y; xv[rr][2] = v.z; xv[rr][3] = v.w;
        }
        #pragma unroll
        for (int kk = 0; kk < 4; kk++) {
            const float4* wr = reinterpret_cast<const float4*>(Ws + (k + kk) * NCLASS);
            #pragma unroll
            for (int c4 = 0; c4 < NCLASS / 4; c4++) {
                float4 ww = wr[c4];
                #pragma unroll
                for (int rr = 0; rr < 2; rr++) {
                    float a = xv[rr][kk];
                    acc[rr][c4*4+0] += a * ww.x;
                    acc[rr][c4*4+1] += a * ww.y;
                    acc[rr][c4*4+2] += a * ww.z;
                    acc[rr][c4*4+3] += a * ww.w;
                }
            }
        }
    }

    #pragma unroll
    for (int rr = 0; rr < 2; rr++) {
        int r = r0 + rr;
        if (r >= nrows) continue;
        float m = acc[rr][0];
        #pragma unroll
        for (int c = 1; c < NCLASS; c++) m = fmaxf(m, acc[rr][c]);
        float s = 0.f;
        #pragma unroll
        for (int c = 0; c < NCLASS; c++) s += __expf(acc[rr][c] - m);
        float lse = m + __logf(s);
        float* op = out + (size_t)r * NCLASS;
        #pragma unroll
        for (int c4 = 0; c4 < NCLASS / 4; c4++) {
            float4 o;
            o.x = acc[rr][c4*4+0] - lse;
            o.y = acc[rr][c4*4+1] - lse;
            o.z = acc[rr][c4*4+2] - lse;
            o.w = acc[rr][c4*4+3] - lse;
            *reinterpret_cast<float4*>(op + c4 * 4) = o;
        }
    }
}

// ---------------------------------------------------------------------------
extern "C" void kernel_launch(void* const* d_in, const int* in_sizes, int n_in,
                              void* d_out, int out_size) {
    const float* x  = (const float*)d_in[0];
    const void*  ei = d_in[1];
    const float* W1 = (const float*)d_in[2];
    const float* b1 = (const float*)d_in[3];
    const float* W2 = (const float*)d_in[4];
    const float* b2 = (const float*)d_in[5];
    const float* Wf = (const float*)d_in[6];
    const float* bf = (const float*)d_in[7];
    float* out = (float*)d_out;

    float *agg, *h;
    int *deg, *off, *cur, *adj, *bsum;
    cudaGetSymbolAddress((void**)&agg,  g_agg);
    cudaGetSymbolAddress((void**)&h,    g_h);
    cudaGetSymbolAddress((void**)&deg,  g_deg);
    cudaGetSymbolAddress((void**)&off,  g_off);
    cudaGetSymbolAddress((void**)&cur,  g_cur);
    cudaGetSymbolAddress((void**)&adj,  g_adj);
    cudaGetSymbolAddress((void**)&bsum, g_bsum);

    const int edge4_blocks = (N_EDGES / 4 + 255) / 256;
    const int agg_blocks   = (N_NODES * 16 + 255) / 256;
    const int gemm_blocks  = (N_NODES + 255) / 256;
    const int fin_blocks   = (N_NODES + 511) / 512;

    // ---- CSR build (once per call, reused by both layers) ----
    cudaMemsetAsync(deg, 0, N_NODES * sizeof(int));
    hist_kernel<<<edge4_blocks, 256>>>(ei, deg);
    scanA_kernel<<<NBLK, SCAN_B>>>(deg, bsum);
    scanC_kernel<<<NBLK, SCAN_B>>>(deg, bsum, off, cur);
    fill_kernel<<<edge4_blocks, 256>>>(ei, cur, adj);

    // ---- Layer 1: agg = x + sum_nbr x ; h = relu(agg @ W1 + b1) ----
    aggregate_kernel<<<agg_blocks, 256>>>(x, agg, off, deg, adj);
    gemm_relu_kernel<<<gemm_blocks, 256>>>(agg, W1, b1, h, N_NODES);

    // ---- Layer 2 ----
    aggregate_kernel<<<agg_blocks, 256>>>(h, agg, off, deg, adj);
    gemm_relu_kernel<<<gemm_blocks, 256>>>(agg, W2, b2, h, N_NODES);

    // ---- Classifier + fused log_softmax ----
    final_kernel<<<fin_blocks, 256>>>(h, Wf, bf, out, N_NODES);
}

// round 16
// speedup vs baseline: 1.0275x; 1.0275x over previous
#include <cuda_runtime.h>
#include <cstdint>

#define N_NODES 100000
#define N_EDGES 1600000
#define NHID 64
#define NCLASS 40
#define SCAN_B 512
#define NBLK ((N_NODES + SCAN_B - 1) / SCAN_B)   // 196

// Scratch (static device globals — no allocation). cnt/cur are 4-way shadow
// counters, interleaved per node: index = node*4 + copy.
// INVARIANT: g_cnt == 0 at kernel_launch entry (zero-init at load; scanC
// re-zeroes after consuming, so every full execution restores it).
__device__ float g_agg[N_NODES * NHID];
__device__ float g_h[N_NODES * NHID];
__device__ int   g_cnt[N_NODES * 4];
__device__ int   g_cur[N_NODES * 4];
__device__ int   g_off[N_NODES + 1];
__device__ int   g_adj[N_EDGES];
__device__ int   g_bsum[NBLK];

// ---------------------------------------------------------------------------
// Edge-index dtype detection (int64 vs x64-disabled int32)
// ---------------------------------------------------------------------------
__device__ __forceinline__ bool ei_is64(const void* ei_raw) {
    const long long* e = (const long long*)ei_raw;
    return ((unsigned long long)e[0] < (1ULL << 32)) &&
           ((unsigned long long)e[1] < (1ULL << 32)) &&
           ((unsigned long long)e[2] < (1ULL << 32));
}
__device__ __forceinline__ int ei_at(const void* ei_raw, bool is64, int i) {
    return is64 ? (int)((const long long*)ei_raw)[i]
                : ((const int*)ei_raw)[i];
}
// Load 4 consecutive indices (i % 4 == 0) from row `row` with vector loads.
__device__ __forceinline__ void ei_load4(const void* ei_raw, bool is64,
                                         int row, int i, int v[4]) {
    if (is64) {
        const longlong2* p =
            (const longlong2*)((const long long*)ei_raw + (size_t)row * N_EDGES + i);
        longlong2 a = p[0], b = p[1];
        v[0] = (int)a.x; v[1] = (int)a.y; v[2] = (int)b.x; v[3] = (int)b.y;
    } else {
        const int4* p = (const int4*)((const int*)ei_raw + (size_t)row * N_EDGES + i);
        int4 a = p[0];
        v[0] = a.x; v[1] = a.y; v[2] = a.z; v[3] = a.w;
    }
}

// ---------------------------------------------------------------------------
// hist: 4 edges/thread; edge e increments shadow copy (e & 3). Same-address
// contention per counter drops from ~16 to ~4.
// ---------------------------------------------------------------------------
__global__ void hist_kernel(const void* __restrict__ ei, int* __restrict__ cnt) {
    int base = (blockIdx.x * blockDim.x + threadIdx.x) * 4;
    if (base >= N_EDGES) return;
    bool is64 = ei_is64(ei);
    int d[4];
    ei_load4(ei, is64, 1, base, d);
    #pragma unroll
    for (int k = 0; k < 4; k++) atomicAdd(&cnt[d[k] * 4 + k], 1);  // c = (base+k)&3 = k
}

// scanA: per-block sums of 512 node-degrees (degree = sum of 4 shadow copies)
__global__ __launch_bounds__(SCAN_B) void scanA_kernel(
    const int* __restrict__ cnt, int* __restrict__ bsum)
{
    __shared__ int s[SCAN_B];
    int t = threadIdx.x;
    int i = blockIdx.x * SCAN_B + t;
    int v = 0;
    if (i < N_NODES) {
        int4 c = ((const int4*)cnt)[i];
        v = c.x + c.y + c.z + c.w;
    }
    s[t] = v;
    __syncthreads();
    #pragma unroll
    for (int k = SCAN_B / 2; k > 0; k >>= 1) {
        if (t < k) s[t] += s[t + k];
        __syncthreads();
    }
    if (t == 0) bsum[blockIdx.x] = s[0];
}

// scanC: fused base-reduction + intra-block scan. Emits off[] (incl. off[N]),
// per-copy cursors cur[] and RE-ZEROES cnt (maintains the entry invariant,
// replacing the memset launch).
__global__ __launch_bounds__(SCAN_B) void scanC_kernel(
    int* __restrict__ cnt, const int* __restrict__ bsum,
    int* __restrict__ off, int* __restrict__ cur)
{
    __shared__ int sa[SCAN_B], sb[SCAN_B];
    int t = threadIdx.x;

    sa[t] = (t < NBLK && t < blockIdx.x) ? bsum[t] : 0;
    __syncthreads();
    #pragma unroll
    for (int k = SCAN_B / 2; k > 0; k >>= 1) {
        if (t < k) sa[t] += sa[t + k];
        __syncthreads();
    }
    int base = sa[0];
    __syncthreads();

    int i = blockIdx.x * SCAN_B + t;
    int4 c4 = make_int4(0, 0, 0, 0);
    if (i < N_NODES) c4 = ((const int4*)cnt)[i];
    int v = c4.x + c4.y + c4.z + c4.w;
    sa[t] = v;
    __syncthreads();
    int* src = sa; int* dst = sb;
    #pragma unroll
    for (int k = 1; k < SCAN_B; k <<= 1) {
        dst[t] = (t >= k) ? src[t] + src[t - k] : src[t];
        __syncthreads();
        int* tmp = src; src = dst; dst = tmp;
    }
    if (i < N_NODES) {
        int excl = base + src[t] - v;
        off[i] = excl;
        if (i == N_NODES - 1) off[N_NODES] = excl + v;
        int4 cu;                                  // per-copy cursor bases
        cu.x = excl;
        cu.y = cu.x + c4.x;
        cu.z = cu.y + c4.y;
        cu.w = cu.z + c4.z;
        ((int4*)cur)[i] = cu;
        ((int4*)cnt)[i] = make_int4(0, 0, 0, 0);  // restore invariant
    }
}

// fill: 1 edge/thread (measured best); edge e uses shadow cursor (e & 3).
__global__ void fill_kernel(const void* __restrict__ ei,
                            int* __restrict__ cur, int* __restrict__ adj) {
    int e = blockIdx.x * blockDim.x + threadIdx.x;
    if (e >= N_EDGES) return;
    bool is64 = ei_is64(ei);
    int s = ei_at(ei, is64, e);
    int d = ei_at(ei, is64, N_EDGES + e);
    int pos = atomicAdd(&cur[d * 4 + (e & 3)], 1);
    adj[pos] = s;
}

// ---------------------------------------------------------------------------
// Pull aggregation: agg[i] = feat[i] + sum_j feat[adj[j]]  (R11 version;
// degree now derived from off[i+1]-off[i]).
// ---------------------------------------------------------------------------
__global__ __launch_bounds__(256) void aggregate_kernel(
    const float* __restrict__ feat, float* __restrict__ aggout,
    const int* __restrict__ off, const int* __restrict__ adj)
{
    int tid = blockIdx.x * blockDim.x + threadIdx.x;
    int node = tid >> 4;
    if (node >= N_NODES) return;
    int q = tid & 15;

    int o = off[node];
    int d = off[node + 1] - o;

    float4 acc = ((const float4*)(feat + (size_t)node * NHID))[q];   // self term

    int i0 = (d > 0) ? __ldg(adj + o) : 0;
    int i1 = (d > 1) ? __ldg(adj + o + 1) : 0;
    for (int j = 0; j < d; j++) {
        int inext = (j + 2 < d) ? __ldg(adj + o + j + 2) : 0;
        float4 v = ((const float4*)(feat + (size_t)i0 * NHID))[q];
        acc.x += v.x; acc.y += v.y; acc.z += v.z; acc.w += v.w;
        i0 = i1; i1 = inext;
    }
    ((float4*)(aggout + (size_t)node * NHID))[q] = acc;
}

// ---------------------------------------------------------------------------
// out = relu(A @ W + b)   (R11 scalar-FFMA version — at fp32 issue floor)
// ---------------------------------------------------------------------------
__global__ __launch_bounds__(256) void gemm_relu_kernel(
    const float* __restrict__ A, const float* __restrict__ W,
    const float* __restrict__ b, float* __restrict__ out, int nrows)
{
    __shared__ __align__(16) float Ws[64 * 64];
    __shared__ float bs[64];
    int t = threadIdx.x;

    const float4* Wg = (const float4*)W;
    float4* Wsv = (float4*)Ws;
    #pragma unroll
    for (int i = 0; i < 4; i++) Wsv[t + i * 256] = Wg[t + i * 256];
    if (t < 64) bs[t] = b[t];
    __syncthreads();

    int cg = t >> 6;
    int rq = t & 63;
    int r0 = blockIdx.x * 256 + rq * 4;

    float acc[4][16];
    #pragma unroll
    for (int rr = 0; rr < 4; rr++)
        #pragma unroll
        for (int c = 0; c < 16; c++) acc[rr][c] = 0.f;

    for (int k = 0; k < 64; k += 4) {
        float xv[4][4];
        #pragma unroll
        for (int rr = 0; rr < 4; rr++) {
            int r = r0 + rr;
            float4 v = (r < nrows)
                ? *reinterpret_cast<const float4*>(A + (size_t)r * 64 + k)
                : make_float4(0.f, 0.f, 0.f, 0.f);
            xv[rr][0] = v.x; xv[rr][1] = v.y; xv[rr][2] = v.z; xv[rr][3] = v.w;
        }
        #pragma unroll
        for (int kk = 0; kk < 4; kk++) {
            const float4* wr = reinterpret_cast<const float4*>(Ws + (k + kk) * 64 + cg * 16);
            float w[16];
            #pragma unroll
            for (int j = 0; j < 4; j++) {
                float4 ww = wr[j];
                w[j*4+0] = ww.x; w[j*4+1] = ww.y; w[j*4+2] = ww.z; w[j*4+3] = ww.w;
            }
            #pragma unroll
            for (int rr = 0; rr < 4; rr++) {
                float a = xv[rr][kk];
                #pragma unroll
                for (int c = 0; c < 16; c++) acc[rr][c] += a * w[c];
            }
        }
    }

    #pragma unroll
    for (int rr = 0; rr < 4; rr++) {
        int r = r0 + rr;
        if (r < nrows) {
            float* op = out + (size_t)r * 64 + cg * 16;
            #pragma unroll
            for (int j = 0; j < 4; j++) {
                float4 o;
                o.x = fmaxf(acc[rr][j*4+0] + bs[cg*16 + j*4+0], 0.f);
                o.y = fmaxf(acc[rr][j*4+1] + bs[cg*16 + j*4+1], 0.f);
                o.z = fmaxf(acc[rr][j*4+2] + bs[cg*16 + j*4+2], 0.f);
                o.w = fmaxf(acc[rr][j*4+3] + bs[cg*16 + j*4+3], 0.f);
                *reinterpret_cast<float4*>(op + j * 4) = o;
            }
        }
    }
}

// ---------------------------------------------------------------------------
// out = log_softmax(A @ Wf + bf)   (R11 version)
// ---------------------------------------------------------------------------
__global__ __launch_bounds__(256) void final_kernel(
    const float* __restrict__ A, const float* __restrict__ W,
    const float* __restrict__ b, float* __restrict__ out, int nrows)
{
    __shared__ __align__(16) float Ws[64 * NCLASS];
    __shared__ float bs[NCLASS];
    int t = threadIdx.x;
    for (int i = t; i < 64 * NCLASS / 4; i += 256)
        ((float4*)Ws)[i] = ((const float4*)W)[i];
    if (t < NCLASS) bs[t] = b[t];
    __syncthreads();

    int r0 = (blockIdx.x * 256 + t) * 2;

    float acc[2][NCLASS];
    #pragma unroll
    for (int rr = 0; rr < 2; rr++)
        #pragma unroll
        for (int c = 0; c < NCLASS; c++) acc[rr][c] = bs[c];

    for (int k = 0; k < 64; k += 4) {
        float xv[2][4];
        #pragma unroll
        for (int rr = 0; rr < 2; rr++) {
            int r = r0 + rr;
            float4 v = (r < nrows)
                ? *reinterpret_cast<const float4*>(A + (size_t)r * 64 + k)
                : make_float4(0.f, 0.f, 0.f, 0.f);
            xv[rr][0] = v.x; xv[rr][1] = v.y; xv[rr][2] = v.z; xv[rr][3] = v.w;
        }
        #pragma unroll
        for (int kk = 0; kk < 4; kk++) {
            const float4* wr = reinterpret_cast<const float4*>(Ws + (k + kk) * NCLASS);
            #pragma unroll
            for (int c4 = 0; c4 < NCLASS / 4; c4++) {
                float4 ww = wr[c4];
                #pragma unroll
                for (int rr = 0; rr < 2; rr++) {
                    float a = xv[rr][kk];
                    acc[rr][c4*4+0] += a * ww.x;
                    acc[rr][c4*4+1] += a * ww.y;
                    acc[rr][c4*4+2] += a * ww.z;
                    acc[rr][c4*4+3] += a * ww.w;
                }
            }
        }
    }

    #pragma unroll
    for (int rr = 0; rr < 2; rr++) {
        int r = r0 + rr;
        if (r >= nrows) continue;
        float m = acc[rr][0];
        #pragma unroll
        for (int c = 1; c < NCLASS; c++) m = fmaxf(m, acc[rr][c]);
        float s = 0.f;
        #pragma unroll
        for (int c = 0; c < NCLASS; c++) s += __expf(acc[rr][c] - m);
        float lse = m + __logf(s);
        float* op = out + (size_t)r * NCLASS;
        #pragma unroll
        for (int c4 = 0; c4 < NCLASS / 4; c4++) {
            float4 o;
            o.x = acc[rr][c4*4+0] - lse;
            o.y = acc[rr][c4*4+1] - lse;
            o.z = acc[rr][c4*4+2] - lse;
            o.w = acc[rr][c4*4+3] - lse;
            *reinterpret_cast<float4*>(op + c4 * 4) = o;
        }
    }
}

// ---------------------------------------------------------------------------
extern "C" void kernel_launch(void* const* d_in, const int* in_sizes, int n_in,
                              void* d_out, int out_size) {
    const float* x  = (const float*)d_in[0];
    const void*  ei = d_in[1];
    const float* W1 = (const float*)d_in[2];
    const float* b1 = (const float*)d_in[3];
    const float* W2 = (const float*)d_in[4];
    const float* b2 = (const float*)d_in[5];
    const float* Wf = (const float*)d_in[6];
    const float* bf = (const float*)d_in[7];
    float* out = (float*)d_out;

    float *agg, *h;
    int *cnt, *off, *cur, *adj, *bsum;
    cudaGetSymbolAddress((void**)&agg,  g_agg);
    cudaGetSymbolAddress((void**)&h,    g_h);
    cudaGetSymbolAddress((void**)&cnt,  g_cnt);
    cudaGetSymbolAddress((void**)&off,  g_off);
    cudaGetSymbolAddress((void**)&cur,  g_cur);
    cudaGetSymbolAddress((void**)&adj,  g_adj);
    cudaGetSymbolAddress((void**)&bsum, g_bsum);

    const int edge_blocks  = (N_EDGES + 255) / 256;
    const int edge4_blocks = (N_EDGES / 4 + 255) / 256;
    const int agg_blocks   = (N_NODES * 16 + 255) / 256;
    const int gemm_blocks  = (N_NODES + 255) / 256;
    const int fin_blocks   = (N_NODES + 511) / 512;

    // ---- CSR build (cnt==0 invariant maintained by scanC; no memset) ----
    hist_kernel<<<edge4_blocks, 256>>>(ei, cnt);
    scanA_kernel<<<NBLK, SCAN_B>>>(cnt, bsum);
    scanC_kernel<<<NBLK, SCAN_B>>>(cnt, bsum, off, cur);
    fill_kernel<<<edge_blocks, 256>>>(ei, cur, adj);

    // ---- Layer 1: agg = x + sum_nbr x ; h = relu(agg @ W1 + b1) ----
    aggregate_kernel<<<agg_blocks, 256>>>(x, agg, off, adj);
    gemm_relu_kernel<<<gemm_blocks, 256>>>(agg, W1, b1, h, N_NODES);

    // ---- Layer 2 ----
    aggregate_kernel<<<agg_blocks, 256>>>(h, agg, off, adj);
    gemm_relu_kernel<<<gemm_blocks, 256>>>(agg, W2, b2, h, N_NODES);

    // ---- Classifier + fused log_softmax ----
    final_kernel<<<fin_blocks, 256>>>(h, Wf, bf, out, N_NODES);
}

// round 17
// speedup vs baseline: 1.0311x; 1.0035x over previous
#include <cuda_runtime.h>
#include <cstdint>

#define N_NODES 100000
#define N_EDGES 1600000
#define NHID 64
#define NCLASS 40
#define SCAN_B 512
#define NBLK ((N_NODES + SCAN_B - 1) / SCAN_B)   // 196

// Scratch (static device globals — no allocation). cnt/cur are 4-way shadow
// counters, interleaved per node: index = node*4 + copy.
// INVARIANT: g_cnt == 0 at kernel_launch entry (zero-init at load; scanC
// re-zeroes after consuming, so every full execution restores it).
__device__ float g_agg[N_NODES * NHID];
__device__ float g_h[N_NODES * NHID];
__device__ int   g_cnt[N_NODES * 4];
__device__ int   g_cur[N_NODES * 4];
__device__ int   g_off[N_NODES + 1];
__device__ int   g_adj[N_EDGES];
__device__ int   g_bsum[NBLK];

// ---------------------------------------------------------------------------
// Edge-index dtype detection (int64 vs x64-disabled int32)
// ---------------------------------------------------------------------------
__device__ __forceinline__ bool ei_is64(const void* ei_raw) {
    const long long* e = (const long long*)ei_raw;
    return ((unsigned long long)e[0] < (1ULL << 32)) &&
           ((unsigned long long)e[1] < (1ULL << 32)) &&
           ((unsigned long long)e[2] < (1ULL << 32));
}
__device__ __forceinline__ int ei_at(const void* ei_raw, bool is64, int i) {
    return is64 ? (int)((const long long*)ei_raw)[i]
                : ((const int*)ei_raw)[i];
}
// Load 4 consecutive indices (i % 4 == 0) from row `row` with vector loads.
__device__ __forceinline__ void ei_load4(const void* ei_raw, bool is64,
                                         int row, int i, int v[4]) {
    if (is64) {
        const longlong2* p =
            (const longlong2*)((const long long*)ei_raw + (size_t)row * N_EDGES + i);
        longlong2 a = p[0], b = p[1];
        v[0] = (int)a.x; v[1] = (int)a.y; v[2] = (int)b.x; v[3] = (int)b.y;
    } else {
        const int4* p = (const int4*)((const int*)ei_raw + (size_t)row * N_EDGES + i);
        int4 a = p[0];
        v[0] = a.x; v[1] = a.y; v[2] = a.z; v[3] = a.w;
    }
}

// ---------------------------------------------------------------------------
// hist: 4 edges/thread; edge e increments shadow copy (e & 3). Same-address
// contention per counter drops from ~16 to ~4.
// ---------------------------------------------------------------------------
__global__ void hist_kernel(const void* __restrict__ ei, int* __restrict__ cnt) {
    int base = (blockIdx.x * blockDim.x + threadIdx.x) * 4;
    if (base >= N_EDGES) return;
    bool is64 = ei_is64(ei);
    int d[4];
    ei_load4(ei, is64, 1, base, d);
    #pragma unroll
    for (int k = 0; k < 4; k++) atomicAdd(&cnt[d[k] * 4 + k], 1);  // c = (base+k)&3 = k
}

// scanA: per-block sums of 512 node-degrees (degree = sum of 4 shadow copies)
__global__ __launch_bounds__(SCAN_B) void scanA_kernel(
    const int* __restrict__ cnt, int* __restrict__ bsum)
{
    __shared__ int s[SCAN_B];
    int t = threadIdx.x;
    int i = blockIdx.x * SCAN_B + t;
    int v = 0;
    if (i < N_NODES) {
        int4 c = ((const int4*)cnt)[i];
        v = c.x + c.y + c.z + c.w;
    }
    s[t] = v;
    __syncthreads();
    #pragma unroll
    for (int k = SCAN_B / 2; k > 0; k >>= 1) {
        if (t < k) s[t] += s[t + k];
        __syncthreads();
    }
    if (t == 0) bsum[blockIdx.x] = s[0];
}

// scanC: fused base-reduction + intra-block scan. Emits off[] (incl. off[N]),
// per-copy cursors cur[] and RE-ZEROES cnt (maintains the entry invariant,
// replacing the memset launch).
__global__ __launch_bounds__(SCAN_B) void scanC_kernel(
    int* __restrict__ cnt, const int* __restrict__ bsum,
    int* __restrict__ off, int* __restrict__ cur)
{
    __shared__ int sa[SCAN_B], sb[SCAN_B];
    int t = threadIdx.x;

    sa[t] = (t < NBLK && t < blockIdx.x) ? bsum[t] : 0;
    __syncthreads();
    #pragma unroll
    for (int k = SCAN_B / 2; k > 0; k >>= 1) {
        if (t < k) sa[t] += sa[t + k];
        __syncthreads();
    }
    int base = sa[0];
    __syncthreads();

    int i = blockIdx.x * SCAN_B + t;
    int4 c4 = make_int4(0, 0, 0, 0);
    if (i < N_NODES) c4 = ((const int4*)cnt)[i];
    int v = c4.x + c4.y + c4.z + c4.w;
    sa[t] = v;
    __syncthreads();
    int* src = sa; int* dst = sb;
    #pragma unroll
    for (int k = 1; k < SCAN_B; k <<= 1) {
        dst[t] = (t >= k) ? src[t] + src[t - k] : src[t];
        __syncthreads();
        int* tmp = src; src = dst; dst = tmp;
    }
    if (i < N_NODES) {
        int excl = base + src[t] - v;
        off[i] = excl;
        if (i == N_NODES - 1) off[N_NODES] = excl + v;
        int4 cu;                                  // per-copy cursor bases
        cu.x = excl;
        cu.y = cu.x + c4.x;
        cu.z = cu.y + c4.y;
        cu.w = cu.z + c4.z;
        ((int4*)cur)[i] = cu;
        ((int4*)cnt)[i] = make_int4(0, 0, 0, 0);  // restore invariant
    }
}

// fill: 1 edge/thread (measured best); edge e uses shadow cursor (e & 3).
__global__ void fill_kernel(const void* __restrict__ ei,
                            int* __restrict__ cur, int* __restrict__ adj) {
    int e = blockIdx.x * blockDim.x + threadIdx.x;
    if (e >= N_EDGES) return;
    bool is64 = ei_is64(ei);
    int s = ei_at(ei, is64, e);
    int d = ei_at(ei, is64, N_EDGES + e);
    int pos = atomicAdd(&cur[d * 4 + (e & 3)], 1);
    adj[pos] = s;
}

// ---------------------------------------------------------------------------
// Pull aggregation: agg[i] = feat[i] + sum_j feat[adj[j]]  (R11 version;
// degree now derived from off[i+1]-off[i]).
// ---------------------------------------------------------------------------
__global__ __launch_bounds__(256) void aggregate_kernel(
    const float* __restrict__ feat, float* __restrict__ aggout,
    const int* __restrict__ off, const int* __restrict__ adj)
{
    int tid = blockIdx.x * blockDim.x + threadIdx.x;
    int node = tid >> 4;
    if (node >= N_NODES) return;
    int q = tid & 15;

    int o = off[node];
    int d = off[node + 1] - o;

    float4 acc = ((const float4*)(feat + (size_t)node * NHID))[q];   // self term

    int i0 = (d > 0) ? __ldg(adj + o) : 0;
    int i1 = (d > 1) ? __ldg(adj + o + 1) : 0;
    for (int j = 0; j < d; j++) {
        int inext = (j + 2 < d) ? __ldg(adj + o + j + 2) : 0;
        float4 v = ((const float4*)(feat + (size_t)i0 * NHID))[q];
        acc.x += v.x; acc.y += v.y; acc.z += v.z; acc.w += v.w;
        i0 = i1; i1 = inext;
    }
    ((float4*)(aggout + (size_t)node * NHID))[q] = acc;
}

// ---------------------------------------------------------------------------
// out = relu(A @ W + b)   (R11 scalar-FFMA version — at fp32 issue floor)
// ---------------------------------------------------------------------------
__global__ __launch_bounds__(256) void gemm_relu_kernel(
    const float* __restrict__ A, const float* __restrict__ W,
    const float* __restrict__ b, float* __restrict__ out, int nrows)
{
    __shared__ __align__(16) float Ws[64 * 64];
    __shared__ float bs[64];
    int t = threadIdx.x;

    const float4* Wg = (const float4*)W;
    float4* Wsv = (float4*)Ws;
    #pragma unroll
    for (int i = 0; i < 4; i++) Wsv[t + i * 256] = Wg[t + i * 256];
    if (t < 64) bs[t] = b[t];
    __syncthreads();

    int cg = t >> 6;
    int rq = t & 63;
    int r0 = blockIdx.x * 256 + rq * 4;

    float acc[4][16];
    #pragma unroll
    for (int rr = 0; rr < 4; rr++)
        #pragma unroll
        for (int c = 0; c < 16; c++) acc[rr][c] = 0.f;

    for (int k = 0; k < 64; k += 4) {
        float xv[4][4];
        #pragma unroll
        for (int rr = 0; rr < 4; rr++) {
            int r = r0 + rr;
            float4 v = (r < nrows)
                ? *reinterpret_cast<const float4*>(A + (size_t)r * 64 + k)
                : make_float4(0.f, 0.f, 0.f, 0.f);
            xv[rr][0] = v.x; xv[rr][1] = v.y; xv[rr][2] = v.z; xv[rr][3] = v.w;
        }
        #pragma unroll
        for (int kk = 0; kk < 4; kk++) {
            const float4* wr = reinterpret_cast<const float4*>(Ws + (k + kk) * 64 + cg * 16);
            float w[16];
            #pragma unroll
            for (int j = 0; j < 4; j++) {
                float4 ww = wr[j];
                w[j*4+0] = ww.x; w[j*4+1] = ww.y; w[j*4+2] = ww.z; w[j*4+3] = ww.w;
            }
            #pragma unroll
            for (int rr = 0; rr < 4; rr++) {
                float a = xv[rr][kk];
                #pragma unroll
                for (int c = 0; c < 16; c++) acc[rr][c] += a * w[c];
            }
        }
    }

    #pragma unroll
    for (int rr = 0; rr < 4; rr++) {
        int r = r0 + rr;
        if (r < nrows) {
            float* op = out + (size_t)r * 64 + cg * 16;
            #pragma unroll
            for (int j = 0; j < 4; j++) {
                float4 o;
                o.x = fmaxf(acc[rr][j*4+0] + bs[cg*16 + j*4+0], 0.f);
                o.y = fmaxf(acc[rr][j*4+1] + bs[cg*16 + j*4+1], 0.f);
                o.z = fmaxf(acc[rr][j*4+2] + bs[cg*16 + j*4+2], 0.f);
                o.w = fmaxf(acc[rr][j*4+3] + bs[cg*16 + j*4+3], 0.f);
                *reinterpret_cast<float4*>(op + j * 4) = o;
            }
        }
    }
}

// ---------------------------------------------------------------------------
// out = log_softmax(A @ Wf + bf)   (R11 version)
// ---------------------------------------------------------------------------
__global__ __launch_bounds__(256) void final_kernel(
    const float* __restrict__ A, const float* __restrict__ W,
    const float* __restrict__ b, float* __restrict__ out, int nrows)
{
    __shared__ __align__(16) float Ws[64 * NCLASS];
    __shared__ float bs[NCLASS];
    int t = threadIdx.x;
    for (int i = t; i < 64 * NCLASS / 4; i += 256)
        ((float4*)Ws)[i] = ((const float4*)W)[i];
    if (t < NCLASS) bs[t] = b[t];
    __syncthreads();

    int r0 = (blockIdx.x * 256 + t) * 2;

    float acc[2][NCLASS];
    #pragma unroll
    for (int rr = 0; rr < 2; rr++)
        #pragma unroll
        for (int c = 0; c < NCLASS; c++) acc[rr][c] = bs[c];

    for (int k = 0; k < 64; k += 4) {
        float xv[2][4];
        #pragma unroll
        for (int rr = 0; rr < 2; rr++) {
            int r = r0 + rr;
            float4 v = (r < nrows)
                ? *reinterpret_cast<const float4*>(A + (size_t)r * 64 + k)
                : make_float4(0.f, 0.f, 0.f, 0.f);
            xv[rr][0] = v.x; xv[rr][1] = v.y; xv[rr][2] = v.z; xv[rr][3] = v.w;
        }
        #pragma unroll
        for (int kk = 0; kk < 4; kk++) {
            const float4* wr = reinterpret_cast<const float4*>(Ws + (k + kk) * NCLASS);
            #pragma unroll
            for (int c4 = 0; c4 < NCLASS / 4; c4++) {
                float4 ww = wr[c4];
                #pragma unroll
                for (int rr = 0; rr < 2; rr++) {
                    float a = xv[rr][kk];
                    acc[rr][c4*4+0] += a * ww.x;
                    acc[rr][c4*4+1] += a * ww.y;
                    acc[rr][c4*4+2] += a * ww.z;
                    acc[rr][c4*4+3] += a * ww.w;
                }
            }
        }
    }

    #pragma unroll
    for (int rr = 0; rr < 2; rr++) {
        int r = r0 + rr;
        if (r >= nrows) continue;
        float m = acc[rr][0];
        #pragma unroll
        for (int c = 1; c < NCLASS; c++) m = fmaxf(m, acc[rr][c]);
        float s = 0.f;
        #pragma unroll
        for (int c = 0; c < NCLASS; c++) s += __expf(acc[rr][c] - m);
        float lse = m + __logf(s);
        float* op = out + (size_t)r * NCLASS;
        #pragma unroll
        for (int c4 = 0; c4 < NCLASS / 4; c4++) {
            float4 o;
            o.x = acc[rr][c4*4+0] - lse;
            o.y = acc[rr][c4*4+1] - lse;
            o.z = acc[rr][c4*4+2] - lse;
            o.w = acc[rr][c4*4+3] - lse;
            *reinterpret_cast<float4*>(op + c4 * 4) = o;
        }
    }
}

// ---------------------------------------------------------------------------
extern "C" void kernel_launch(void* const* d_in, const int* in_sizes, int n_in,
                              void* d_out, int out_size) {
    const float* x  = (const float*)d_in[0];
    const void*  ei = d_in[1];
    const float* W1 = (const float*)d_in[2];
    const float* b1 = (const float*)d_in[3];
    const float* W2 = (const float*)d_in[4];
    const float* b2 = (const float*)d_in[5];
    const float* Wf = (const float*)d_in[6];
    const float* bf = (const float*)d_in[7];
    float* out = (float*)d_out;

    float *agg, *h;
    int *cnt, *off, *cur, *adj, *bsum;
    cudaGetSymbolAddress((void**)&agg,  g_agg);
    cudaGetSymbolAddress((void**)&h,    g_h);
    cudaGetSymbolAddress((void**)&cnt,  g_cnt);
    cudaGetSymbolAddress((void**)&off,  g_off);
    cudaGetSymbolAddress((void**)&cur,  g_cur);
    cudaGetSymbolAddress((void**)&adj,  g_adj);
    cudaGetSymbolAddress((void**)&bsum, g_bsum);

    const int edge_blocks  = (N_EDGES + 255) / 256;
    const int edge4_blocks = (N_EDGES / 4 + 255) / 256;
    const int agg_blocks   = (N_NODES * 16 + 255) / 256;
    const int gemm_blocks  = (N_NODES + 255) / 256;
    const int fin_blocks   = (N_NODES + 511) / 512;

    // ---- CSR build (cnt==0 invariant maintained by scanC; no memset) ----
    hist_kernel<<<edge4_blocks, 256>>>(ei, cnt);
    scanA_kernel<<<NBLK, SCAN_B>>>(cnt, bsum);
    scanC_kernel<<<NBLK, SCAN_B>>>(cnt, bsum, off, cur);
    fill_kernel<<<edge_blocks, 256>>>(ei, cur, adj);

    // ---- Layer 1: agg = x + sum_nbr x ; h = relu(agg @ W1 + b1) ----
    aggregate_kernel<<<agg_blocks, 256>>>(x, agg, off, adj);
    gemm_relu_kernel<<<gemm_blocks, 256>>>(agg, W1, b1, h, N_NODES);

    // ---- Layer 2 ----
    aggregate_kernel<<<agg_blocks, 256>>>(h, agg, off, adj);
    gemm_relu_kernel<<<gemm_blocks, 256>>>(agg, W2, b2, h, N_NODES);

    // ---- Classifier + fused log_softmax ----
    final_kernel<<<fin_blocks, 256>>>(h, Wf, bf, out, N_NODES);
}